// round 2
// baseline (speedup 1.0000x reference)
#include <cuda_runtime.h>
#include <cuda_bf16.h>

// ---------------------------------------------------------------------------
// Problem constants
// ---------------------------------------------------------------------------
#define S_LEN   2048
#define D_MODEL 2048
#define NHEADS  32
#define NKV     8
#define DHEAD   64
#define WIN     1024
#define GROUP   4            // NHEADS / NKV
#define BATCH   2
#define MROWS   (BATCH * S_LEN)   // 4096
#define KVD     (NKV * DHEAD)     // 512

// Scratch (device globals — no allocation allowed)
__device__ float g_q [MROWS * D_MODEL];   // 33.5 MB
__device__ float g_k [MROWS * KVD];       //  8.4 MB
__device__ float g_v [MROWS * KVD];       //  8.4 MB
__device__ float g_ao[MROWS * D_MODEL];   // 33.5 MB

// ---------------------------------------------------------------------------
// SGEMM: C[M,N] = A[M,K] @ W[N,K]^T + bias[N]
// 128x128 tile, BK=8, 256 threads, 8x8 per-thread, double-buffered smem.
// M, N, K all multiples of 128/8 for our shapes.
// ---------------------------------------------------------------------------
__global__ __launch_bounds__(256, 2)
void sgemm_nt_bias(const float* __restrict__ A, const float* __restrict__ W,
                   const float* __restrict__ bias, float* __restrict__ C,
                   int M, int N, int K)
{
    __shared__ __align__(16) float As[2][8][128];
    __shared__ __align__(16) float Bs[2][8][128];

    const int tid = threadIdx.x;
    const int tx  = tid & 15;        // C column group (8 cols)
    const int ty  = tid >> 4;        // C row group (8 rows)
    const int m0  = blockIdx.x * 128;
    const int n0  = blockIdx.y * 128;

    // tile-load mapping: each thread loads one float4 of A and one of W
    const int lrow = tid >> 1;           // 0..127
    const int lcol = (tid & 1) * 4;      // 0 or 4
    const float* Ap = A + (size_t)(m0 + lrow) * K + lcol;
    const float* Wp = W + (size_t)(n0 + lrow) * K + lcol;

    float acc[8][8];
    #pragma unroll
    for (int i = 0; i < 8; ++i)
        #pragma unroll
        for (int j = 0; j < 8; ++j) acc[i][j] = 0.0f;

    const int ntiles = K >> 3;

    // preload tile 0
    float4 a4 = *(const float4*)Ap;
    float4 b4 = *(const float4*)Wp;
    As[0][lcol + 0][lrow] = a4.x;  As[0][lcol + 1][lrow] = a4.y;
    As[0][lcol + 2][lrow] = a4.z;  As[0][lcol + 3][lrow] = a4.w;
    Bs[0][lcol + 0][lrow] = b4.x;  Bs[0][lcol + 1][lrow] = b4.y;
    Bs[0][lcol + 2][lrow] = b4.z;  Bs[0][lcol + 3][lrow] = b4.w;
    __syncthreads();

    int buf = 0;
    for (int t = 0; t < ntiles; ++t) {
        if (t + 1 < ntiles) {
            a4 = *(const float4*)(Ap + (size_t)(t + 1) * 8);
            b4 = *(const float4*)(Wp + (size_t)(t + 1) * 8);
        }
        #pragma unroll
        for (int kk = 0; kk < 8; ++kk) {
            float4 af0 = *(const float4*)&As[buf][kk][ty * 8];
            float4 af1 = *(const float4*)&As[buf][kk][ty * 8 + 4];
            float4 bf0 = *(const float4*)&Bs[buf][kk][tx * 8];
            float4 bf1 = *(const float4*)&Bs[buf][kk][tx * 8 + 4];
            float ar[8] = {af0.x, af0.y, af0.z, af0.w, af1.x, af1.y, af1.z, af1.w};
            float br[8] = {bf0.x, bf0.y, bf0.z, bf0.w, bf1.x, bf1.y, bf1.z, bf1.w};
            #pragma unroll
            for (int i = 0; i < 8; ++i)
                #pragma unroll
                for (int j = 0; j < 8; ++j)
                    acc[i][j] = fmaf(ar[i], br[j], acc[i][j]);
        }
        if (t + 1 < ntiles) {
            const int nb = buf ^ 1;
            As[nb][lcol + 0][lrow] = a4.x;  As[nb][lcol + 1][lrow] = a4.y;
            As[nb][lcol + 2][lrow] = a4.z;  As[nb][lcol + 3][lrow] = a4.w;
            Bs[nb][lcol + 0][lrow] = b4.x;  Bs[nb][lcol + 1][lrow] = b4.y;
            Bs[nb][lcol + 2][lrow] = b4.z;  Bs[nb][lcol + 3][lrow] = b4.w;
            __syncthreads();
            buf = nb;
        }
    }

    // epilogue: + bias, vectorized stores
    float bj[8];
    #pragma unroll
    for (int j = 0; j < 8; ++j) bj[j] = bias[n0 + tx * 8 + j];

    #pragma unroll
    for (int i = 0; i < 8; ++i) {
        const int row = m0 + ty * 8 + i;
        float* Cp = C + (size_t)row * N + n0 + tx * 8;
        float4 o0 = make_float4(acc[i][0] + bj[0], acc[i][1] + bj[1],
                                acc[i][2] + bj[2], acc[i][3] + bj[3]);
        float4 o1 = make_float4(acc[i][4] + bj[4], acc[i][5] + bj[5],
                                acc[i][6] + bj[6], acc[i][7] + bj[7]);
        *(float4*)(Cp)     = o0;
        *(float4*)(Cp + 4) = o1;
    }
}

// ---------------------------------------------------------------------------
// Flash attention with sliding window + ALiBi + GQA.
// One CTA = (q-tile of 64 rows, head h, batch b). 256 threads.
// 16x16 thread grid; each thread owns a 4x4 S/P frag and 4x4 O frag.
// Row-softmax reduced across the 16 lanes sharing a row group via shfl.xor.
// smem: Qt[d][i], Kt[d][j], Vs[j][d], Pt[j][i]  (stride 68 floats each)
// ---------------------------------------------------------------------------
#define TQ 64
#define TK 64
#define SMS 68    // padded stride
#define ATTN_SMEM (4 * 64 * SMS * 4)

__global__ __launch_bounds__(256, 1)
void attn_kernel(const float* __restrict__ alibi)
{
    extern __shared__ __align__(16) float sm[];
    float* Qt = sm;
    float* Kt = sm + 64 * SMS;
    float* Vs = sm + 2 * 64 * SMS;
    float* Pt = sm + 3 * 64 * SMS;

    const int tid = threadIdx.x;
    const int tx  = tid & 15;     // column direction (k / dh)
    const int ty  = tid >> 4;     // row direction (q)
    const int i0  = blockIdx.x * TQ;
    const int h   = blockIdx.y;
    const int b   = blockIdx.z;
    const int hkv = h >> 2;       // GROUP = 4
    const float slope = alibi[h];
    const float scale = 0.125f;   // 1/sqrt(64)

    // ---- load Q tile transposed: Qt[d][i] ----
    const size_t qbase = (size_t)(b * S_LEN + i0) * D_MODEL + h * DHEAD;
    #pragma unroll
    for (int r = 0; r < 4; ++r) {
        const int idx = tid + r * 256;
        const int i   = idx >> 4;
        const int d4  = (idx & 15) * 4;
        float4 q4 = *(const float4*)&g_q[qbase + (size_t)i * D_MODEL + d4];
        Qt[(d4 + 0) * SMS + i] = q4.x;
        Qt[(d4 + 1) * SMS + i] = q4.y;
        Qt[(d4 + 2) * SMS + i] = q4.z;
        Qt[(d4 + 3) * SMS + i] = q4.w;
    }

    float o[4][4];
    #pragma unroll
    for (int i = 0; i < 4; ++i)
        #pragma unroll
        for (int j = 0; j < 4; ++j) o[i][j] = 0.0f;
    float mrow[4] = {-1e30f, -1e30f, -1e30f, -1e30f};
    float lrow[4] = {0.0f, 0.0f, 0.0f, 0.0f};

    const int jt_lo = max(0, i0 - (WIN - 1)) >> 6;
    const int jt_hi = i0 >> 6;
    const size_t kvbase = (size_t)(b * S_LEN) * KVD + hkv * DHEAD;

    __syncthreads();   // Qt ready

    for (int jt = jt_lo; jt <= jt_hi; ++jt) {
        const int j0 = jt << 6;

        // ---- load K tile transposed Kt[d][j], V tile row-major Vs[j][d] ----
        #pragma unroll
        for (int r = 0; r < 4; ++r) {
            const int idx = tid + r * 256;
            const int j   = idx >> 4;
            const int d4  = (idx & 15) * 4;
            const size_t g = kvbase + (size_t)(j0 + j) * KVD + d4;
            float4 k4 = *(const float4*)&g_k[g];
            Kt[(d4 + 0) * SMS + j] = k4.x;
            Kt[(d4 + 1) * SMS + j] = k4.y;
            Kt[(d4 + 2) * SMS + j] = k4.z;
            Kt[(d4 + 3) * SMS + j] = k4.w;
            float4 v4 = *(const float4*)&g_v[g];
            *(float4*)&Vs[j * SMS + d4] = v4;
        }
        __syncthreads();

        // ---- S = Q @ K^T (4x4 frag per thread) ----
        float s[4][4];
        #pragma unroll
        for (int i = 0; i < 4; ++i)
            #pragma unroll
            for (int j = 0; j < 4; ++j) s[i][j] = 0.0f;

        #pragma unroll 16
        for (int d = 0; d < 64; ++d) {
            float4 qa = *(const float4*)&Qt[d * SMS + ty * 4];
            float4 kb = *(const float4*)&Kt[d * SMS + tx * 4];
            float qr[4] = {qa.x, qa.y, qa.z, qa.w};
            float kr[4] = {kb.x, kb.y, kb.z, kb.w};
            #pragma unroll
            for (int ii = 0; ii < 4; ++ii)
                #pragma unroll
                for (int jj = 0; jj < 4; ++jj)
                    s[ii][jj] = fmaf(qr[ii], kr[jj], s[ii][jj]);
        }

        // ---- scale + ALiBi + sliding-window causal mask ----
        const int gi0 = i0 + ty * 4;
        const int gj0 = j0 + tx * 4;
        #pragma unroll
        for (int ii = 0; ii < 4; ++ii) {
            const int gi = gi0 + ii;
            #pragma unroll
            for (int jj = 0; jj < 4; ++jj) {
                const int dlt = gi - (gj0 + jj);           // i - j
                const bool valid = (dlt >= 0) && (dlt < WIN);
                s[ii][jj] = valid ? fmaf(s[ii][jj], scale, -slope * (float)dlt)
                                  : -1e30f;
            }
        }

        // ---- online softmax (row reduce over 16 lanes per row group) ----
        #pragma unroll
        for (int ii = 0; ii < 4; ++ii) {
            float mx = fmaxf(fmaxf(s[ii][0], s[ii][1]), fmaxf(s[ii][2], s[ii][3]));
            mx = fmaxf(mx, __shfl_xor_sync(0xffffffffu, mx, 1));
            mx = fmaxf(mx, __shfl_xor_sync(0xffffffffu, mx, 2));
            mx = fmaxf(mx, __shfl_xor_sync(0xffffffffu, mx, 4));
            mx = fmaxf(mx, __shfl_xor_sync(0xffffffffu, mx, 8));
            const float newm = fmaxf(mrow[ii], mx);
            const float corr = __expf(mrow[ii] - newm);   // 1 if both -1e30
            mrow[ii] = newm;
            float rs = 0.0f;
            #pragma unroll
            for (int jj = 0; jj < 4; ++jj) {
                const float p = (s[ii][jj] > -1e29f) ? __expf(s[ii][jj] - newm) : 0.0f;
                s[ii][jj] = p;
                rs += p;
            }
            rs += __shfl_xor_sync(0xffffffffu, rs, 1);
            rs += __shfl_xor_sync(0xffffffffu, rs, 2);
            rs += __shfl_xor_sync(0xffffffffu, rs, 4);
            rs += __shfl_xor_sync(0xffffffffu, rs, 8);
            lrow[ii] = lrow[ii] * corr + rs;
            #pragma unroll
            for (int c = 0; c < 4; ++c) o[ii][c] *= corr;
        }

        // ---- stage P transposed: Pt[j][i] ----
        #pragma unroll
        for (int jj = 0; jj < 4; ++jj)
            #pragma unroll
            for (int ii = 0; ii < 4; ++ii)
                Pt[(tx * 4 + jj) * SMS + ty * 4 + ii] = s[ii][jj];
        __syncthreads();

        // ---- O += P @ V ----
        #pragma unroll 16
        for (int j = 0; j < 64; ++j) {
            float4 pa = *(const float4*)&Pt[j * SMS + ty * 4];
            float4 vb = *(const float4*)&Vs[j * SMS + tx * 4];
            float pr[4] = {pa.x, pa.y, pa.z, pa.w};
            float vr[4] = {vb.x, vb.y, vb.z, vb.w};
            #pragma unroll
            for (int ii = 0; ii < 4; ++ii)
                #pragma unroll
                for (int c = 0; c < 4; ++c)
                    o[ii][c] = fmaf(pr[ii], vr[c], o[ii][c]);
        }
        __syncthreads();
    }

    // ---- normalize and write [B,S,H,DH] as [4096, 2048] ----
    #pragma unroll
    for (int ii = 0; ii < 4; ++ii) {
        const float inv = 1.0f / lrow[ii];
        float4 r = make_float4(o[ii][0] * inv, o[ii][1] * inv,
                               o[ii][2] * inv, o[ii][3] * inv);
        const size_t off = (size_t)(b * S_LEN + i0 + ty * 4 + ii) * D_MODEL
                         + h * DHEAD + tx * 4;
        *(float4*)&g_ao[off] = r;
    }
}

// ---------------------------------------------------------------------------
// Launch
// ---------------------------------------------------------------------------
extern "C" void kernel_launch(void* const* d_in, const int* in_sizes, int n_in,
                              void* d_out, int out_size)
{
    const float* x     = (const float*)d_in[0];
    const float* Wq    = (const float*)d_in[1];
    const float* bq    = (const float*)d_in[2];
    const float* Wk    = (const float*)d_in[3];
    const float* bk    = (const float*)d_in[4];
    const float* Wv    = (const float*)d_in[5];
    const float* bv    = (const float*)d_in[6];
    const float* Wo    = (const float*)d_in[7];
    const float* bo    = (const float*)d_in[8];
    const float* alibi = (const float*)d_in[9];
    float* out = (float*)d_out;

    float *q, *k, *v, *ao;
    cudaGetSymbolAddress((void**)&q,  g_q);
    cudaGetSymbolAddress((void**)&k,  g_k);
    cudaGetSymbolAddress((void**)&v,  g_v);
    cudaGetSymbolAddress((void**)&ao, g_ao);

    cudaFuncSetAttribute(attn_kernel,
                         cudaFuncAttributeMaxDynamicSharedMemorySize, ATTN_SMEM);

    dim3 blk(256);
    // QKV projections
    sgemm_nt_bias<<<dim3(32, 16), blk>>>(x, Wq, bq, q, MROWS, D_MODEL, D_MODEL);
    sgemm_nt_bias<<<dim3(32, 4),  blk>>>(x, Wk, bk, k, MROWS, KVD,     D_MODEL);
    sgemm_nt_bias<<<dim3(32, 4),  blk>>>(x, Wv, bv, v, MROWS, KVD,     D_MODEL);
    // attention
    attn_kernel<<<dim3(S_LEN / TQ, NHEADS, BATCH), blk, ATTN_SMEM>>>(alibi);
    // output projection
    sgemm_nt_bias<<<dim3(32, 16), blk>>>(ao, Wo, bo, out, MROWS, D_MODEL, D_MODEL);
}

// round 6
// speedup vs baseline: 2.2939x; 2.2939x over previous
#include <cuda_runtime.h>
#include <cuda_bf16.h>
#include <cstdint>

// ---------------------------------------------------------------------------
// Problem constants
// ---------------------------------------------------------------------------
#define S_LEN   2048
#define D_MODEL 2048
#define NHEADS  32
#define NKV     8
#define DHEAD   64
#define WIN     1024
#define BATCH   2
#define MROWS   (BATCH * S_LEN)   // 4096
#define KVD     (NKV * DHEAD)     // 512

// Scratch (device globals — no allocation allowed)
__device__ float g_q [MROWS * D_MODEL];
__device__ float g_k [MROWS * KVD];
__device__ float g_v [MROWS * KVD];
__device__ float g_ao[MROWS * D_MODEL];
// tf32-rounded copies of GEMM inputs
__device__ float g_x [MROWS * D_MODEL];
__device__ float g_wq[D_MODEL * D_MODEL];
__device__ float g_wk[KVD * D_MODEL];
__device__ float g_wv[KVD * D_MODEL];
__device__ float g_wo[D_MODEL * D_MODEL];

// ---------------------------------------------------------------------------
// Helpers
// ---------------------------------------------------------------------------
__device__ __forceinline__ uint32_t smem_to_u32(const void* p) {
    uint32_t a;
    asm("{ .reg .u64 t; cvta.to.shared.u64 t, %1; cvt.u32.u64 %0, t; }"
        : "=r"(a) : "l"(p));
    return a;
}
__device__ __forceinline__ float rna_tf32(float x) {
    uint32_t u;
    asm("cvt.rna.tf32.f32 %0, %1;" : "=r"(u) : "f"(x));
    return __uint_as_float(u);
}

#define CP_ASYNC_CG(dst, src) \
    asm volatile("cp.async.cg.shared.global [%0], [%1], 16;" \
        :: "r"(dst), "l"(src))
#define CP_COMMIT() asm volatile("cp.async.commit_group;" ::: "memory")
#define CP_WAIT(n)  asm volatile("cp.async.wait_group %0;" :: "n"(n) : "memory")

#define LDSM_X4(r0, r1, r2, r3, addr) \
    asm volatile("ldmatrix.sync.aligned.m8n8.x4.shared.b16 {%0,%1,%2,%3}, [%4];" \
        : "=r"(r0), "=r"(r1), "=r"(r2), "=r"(r3) : "r"(addr))

#define MMA_TF32(d, a0, a1, a2, a3, b0, b1) \
    asm volatile("mma.sync.aligned.m16n8k8.row.col.f32.tf32.tf32.f32 " \
        "{%0,%1,%2,%3},{%4,%5,%6,%7},{%8,%9},{%0,%1,%2,%3};" \
        : "+f"((d)[0]), "+f"((d)[1]), "+f"((d)[2]), "+f"((d)[3]) \
        : "r"(a0), "r"(a1), "r"(a2), "r"(a3), "r"(b0), "r"(b1))

// ---------------------------------------------------------------------------
// tf32-rounding pre-pass
// ---------------------------------------------------------------------------
__global__ void round_tf32_kernel(const float* __restrict__ in,
                                  float* __restrict__ out, int n4)
{
    for (int i = blockIdx.x * blockDim.x + threadIdx.x; i < n4;
         i += gridDim.x * blockDim.x) {
        float4 v = ((const float4*)in)[i];
        v.x = rna_tf32(v.x); v.y = rna_tf32(v.y);
        v.z = rna_tf32(v.z); v.w = rna_tf32(v.w);
        ((float4*)out)[i] = v;
    }
}

// ---------------------------------------------------------------------------
// tf32 mma.sync GEMM: C[M,N] = A[M,K] @ W[N,K]^T + bias[N]
// CTA tile 128x128, BK=16, 4-stage cp.async pipeline, 8 warps (2m x 4n),
// warp tile 64x32 (4 m-frags x 4 n-frags of m16n8k8).
// smem stage: A[128][16] + B[128][16] floats, 64B rows, chunk-XOR swizzle.
// ---------------------------------------------------------------------------
#define GSTAGES 4
#define GSTAGE_BYTES 16384          // 8KB A + 8KB B
#define GEMM_SMEM (GSTAGES * GSTAGE_BYTES)   // 64KB

__device__ __forceinline__ void gemm_load_stage(
    uint32_t smem_u, const float* __restrict__ A, const float* __restrict__ W,
    int K, int m0, int n0, int t, int tid)
{
    const uint32_t base = smem_u + (t & (GSTAGES - 1)) * GSTAGE_BYTES;
    const int k0 = t * 16;
    #pragma unroll
    for (int i = 0; i < 4; ++i) {
        const int id  = tid + i * 256;        // 0..1023
        const int isB = id >> 9;              // 0: A, 1: B
        const int id2 = id & 511;
        const int row = id2 >> 2;             // 0..127
        const int c   = id2 & 3;              // 16B chunk within row
        const float* src = (isB ? W + (size_t)(n0 + row) * K
                                : A + (size_t)(m0 + row) * K) + k0 + c * 4;
        const uint32_t dst = base + (isB ? 8192 : 0) + row * 64
                           + ((c ^ ((row >> 1) & 3)) * 16);
        CP_ASYNC_CG(dst, src);
    }
}

__device__ __forceinline__ void gemm_tile_mma(
    const float* __restrict__ A, const float* __restrict__ W,
    const float* __restrict__ bias, float* __restrict__ C,
    int ldc, int K, int m0, int n0, char* smem)
{
    const uint32_t smem_u = smem_to_u32(smem);
    const int tid    = threadIdx.x;
    const int lane   = tid & 31;
    const int wid    = tid >> 5;
    const int warp_m = wid >> 2;      // 0..1  -> 64 rows
    const int warp_n = wid & 3;       // 0..3  -> 32 cols

    // precompute ldmatrix per-thread smem offsets
    // A frag (fm, ks): rows warp_m*64 + fm*16 + ((lane>>3)&1)*8 + (lane&7)
    //                  chunk 2*ks + (lane>>4)
    int offA[4][2], offB[2][2];
    {
        const int arow_lo = ((lane >> 3) & 1) * 8 + (lane & 7);
        const int ahi     = lane >> 4;                 // 0/1
        #pragma unroll
        for (int fm = 0; fm < 4; ++fm) {
            const int row = warp_m * 64 + fm * 16 + arow_lo;
            const int sw  = (row >> 1) & 3;
            #pragma unroll
            for (int ks = 0; ks < 2; ++ks) {
                const int chunk = 2 * ks + ahi;
                offA[fm][ks] = row * 64 + ((chunk ^ sw) & 3) * 16;
            }
        }
        const int brow_lo = ((lane >> 4) & 1) * 8 + (lane & 7);
        const int bhi     = (lane >> 3) & 1;
        #pragma unroll
        for (int p = 0; p < 2; ++p) {
            const int row = warp_n * 32 + p * 16 + brow_lo;
            const int sw  = (row >> 1) & 3;
            #pragma unroll
            for (int ks = 0; ks < 2; ++ks) {
                const int chunk = 2 * ks + bhi;
                offB[p][ks] = row * 64 + ((chunk ^ sw) & 3) * 16;
            }
        }
    }

    float acc[4][4][4];
    #pragma unroll
    for (int i = 0; i < 4; ++i)
        #pragma unroll
        for (int j = 0; j < 4; ++j)
            #pragma unroll
            for (int r = 0; r < 4; ++r) acc[i][j][r] = 0.0f;

    const int T = K >> 4;   // 128 stages

    // prologue: fill stages 0..GSTAGES-2
    #pragma unroll
    for (int s = 0; s < GSTAGES - 1; ++s) {
        gemm_load_stage(smem_u, A, W, K, m0, n0, s, tid);
        CP_COMMIT();
    }

    for (int t = 0; t < T; ++t) {
        CP_WAIT(GSTAGES - 2);
        __syncthreads();

        if (t + GSTAGES - 1 < T)
            gemm_load_stage(smem_u, A, W, K, m0, n0, t + GSTAGES - 1, tid);
        CP_COMMIT();

        const uint32_t sA = smem_u + (t & (GSTAGES - 1)) * GSTAGE_BYTES;
        const uint32_t sB = sA + 8192;

        #pragma unroll
        for (int ks = 0; ks < 2; ++ks) {
            uint32_t a[4][4], b[2][4];
            #pragma unroll
            for (int fm = 0; fm < 4; ++fm)
                LDSM_X4(a[fm][0], a[fm][1], a[fm][2], a[fm][3],
                        sA + offA[fm][ks]);
            #pragma unroll
            for (int p = 0; p < 2; ++p)
                LDSM_X4(b[p][0], b[p][1], b[p][2], b[p][3],
                        sB + offB[p][ks]);
            #pragma unroll
            for (int fm = 0; fm < 4; ++fm) {
                #pragma unroll
                for (int fn = 0; fn < 4; ++fn) {
                    const int p  = fn >> 1;
                    const int r0 = (fn & 1) * 2;
                    MMA_TF32(acc[fm][fn], a[fm][0], a[fm][1], a[fm][2],
                             a[fm][3], b[p][r0], b[p][r0 + 1]);
                }
            }
        }
    }

    // epilogue: + bias, float2 stores
    const int trow = lane >> 2;
    const int tcol = (lane & 3) * 2;
    #pragma unroll
    for (int fm = 0; fm < 4; ++fm) {
        const int row = m0 + warp_m * 64 + fm * 16 + trow;
        #pragma unroll
        for (int fn = 0; fn < 4; ++fn) {
            const int col = n0 + warp_n * 32 + fn * 8 + tcol;
            const float2 bb = *(const float2*)(bias + col);
            float2 lo = make_float2(acc[fm][fn][0] + bb.x,
                                    acc[fm][fn][1] + bb.y);
            float2 hi = make_float2(acc[fm][fn][2] + bb.x,
                                    acc[fm][fn][3] + bb.y);
            *(float2*)(C + (size_t)row * ldc + col)       = lo;
            *(float2*)(C + (size_t)(row + 8) * ldc + col) = hi;
        }
    }
}

// Fused QKV projection: grid (32, 24). y<16 -> Q, y<20 -> K, else V.
__global__ __launch_bounds__(256, 2)
void qkv_kernel(const float* __restrict__ bq, const float* __restrict__ bk,
                const float* __restrict__ bv)
{
    extern __shared__ __align__(128) char smem[];
    const int y = blockIdx.y;
    const float *W, *bias;
    float* C;
    int ldc, n0;
    if (y < 16)      { W = g_wq; bias = bq; C = g_q; ldc = D_MODEL; n0 = y * 128; }
    else if (y < 20) { W = g_wk; bias = bk; C = g_k; ldc = KVD;     n0 = (y - 16) * 128; }
    else             { W = g_wv; bias = bv; C = g_v; ldc = KVD;     n0 = (y - 20) * 128; }
    gemm_tile_mma(g_x, W, bias, C, ldc, D_MODEL, blockIdx.x * 128, n0, smem);
}

// Output projection: grid (32, 16)
__global__ __launch_bounds__(256, 2)
void oproj_kernel(const float* __restrict__ bo, float* __restrict__ out)
{
    extern __shared__ __align__(128) char smem[];
    gemm_tile_mma(g_ao, g_wo, bo, out, D_MODEL, D_MODEL,
                  blockIdx.x * 128, blockIdx.y * 128, smem);
}

// ---------------------------------------------------------------------------
// Flash attention with sliding window + ALiBi + GQA (fp32 FFMA; output
// rounded to tf32 so the O-projection mma sees RNA-rounded inputs).
// ---------------------------------------------------------------------------
#define TQ 64
#define SMS 68
#define ATTN_SMEM (4 * 64 * SMS * 4)

__global__ __launch_bounds__(256, 1)
void attn_kernel(const float* __restrict__ alibi)
{
    extern __shared__ __align__(16) float sm[];
    float* Qt = sm;
    float* Kt = sm + 64 * SMS;
    float* Vs = sm + 2 * 64 * SMS;
    float* Pt = sm + 3 * 64 * SMS;

    const int tid = threadIdx.x;
    const int tx  = tid & 15;
    const int ty  = tid >> 4;
    const int i0  = blockIdx.x * TQ;
    const int h   = blockIdx.y;
    const int b   = blockIdx.z;
    const int hkv = h >> 2;
    const float slope = alibi[h];
    const float scale = 0.125f;

    const size_t qbase = (size_t)(b * S_LEN + i0) * D_MODEL + h * DHEAD;
    #pragma unroll
    for (int r = 0; r < 4; ++r) {
        const int idx = tid + r * 256;
        const int i   = idx >> 4;
        const int d4  = (idx & 15) * 4;
        float4 q4 = *(const float4*)&g_q[qbase + (size_t)i * D_MODEL + d4];
        Qt[(d4 + 0) * SMS + i] = q4.x;
        Qt[(d4 + 1) * SMS + i] = q4.y;
        Qt[(d4 + 2) * SMS + i] = q4.z;
        Qt[(d4 + 3) * SMS + i] = q4.w;
    }

    float o[4][4];
    #pragma unroll
    for (int i = 0; i < 4; ++i)
        #pragma unroll
        for (int j = 0; j < 4; ++j) o[i][j] = 0.0f;
    float mrow[4] = {-1e30f, -1e30f, -1e30f, -1e30f};
    float lrow[4] = {0.0f, 0.0f, 0.0f, 0.0f};

    const int jt_lo = max(0, i0 - (WIN - 1)) >> 6;
    const int jt_hi = i0 >> 6;
    const size_t kvbase = (size_t)(b * S_LEN) * KVD + hkv * DHEAD;

    __syncthreads();

    for (int jt = jt_lo; jt <= jt_hi; ++jt) {
        const int j0 = jt << 6;
        #pragma unroll
        for (int r = 0; r < 4; ++r) {
            const int idx = tid + r * 256;
            const int j   = idx >> 4;
            const int d4  = (idx & 15) * 4;
            const size_t g = kvbase + (size_t)(j0 + j) * KVD + d4;
            float4 k4 = *(const float4*)&g_k[g];
            Kt[(d4 + 0) * SMS + j] = k4.x;
            Kt[(d4 + 1) * SMS + j] = k4.y;
            Kt[(d4 + 2) * SMS + j] = k4.z;
            Kt[(d4 + 3) * SMS + j] = k4.w;
            float4 v4 = *(const float4*)&g_v[g];
            *(float4*)&Vs[j * SMS + d4] = v4;
        }
        __syncthreads();

        float s[4][4];
        #pragma unroll
        for (int i = 0; i < 4; ++i)
            #pragma unroll
            for (int j = 0; j < 4; ++j) s[i][j] = 0.0f;

        #pragma unroll 16
        for (int d = 0; d < 64; ++d) {
            float4 qa = *(const float4*)&Qt[d * SMS + ty * 4];
            float4 kb = *(const float4*)&Kt[d * SMS + tx * 4];
            float qr[4] = {qa.x, qa.y, qa.z, qa.w};
            float kr[4] = {kb.x, kb.y, kb.z, kb.w};
            #pragma unroll
            for (int ii = 0; ii < 4; ++ii)
                #pragma unroll
                for (int jj = 0; jj < 4; ++jj)
                    s[ii][jj] = fmaf(qr[ii], kr[jj], s[ii][jj]);
        }

        const int gi0 = i0 + ty * 4;
        const int gj0 = j0 + tx * 4;
        #pragma unroll
        for (int ii = 0; ii < 4; ++ii) {
            const int gi = gi0 + ii;
            #pragma unroll
            for (int jj = 0; jj < 4; ++jj) {
                const int dlt = gi - (gj0 + jj);
                const bool valid = (dlt >= 0) && (dlt < WIN);
                s[ii][jj] = valid ? fmaf(s[ii][jj], scale, -slope * (float)dlt)
                                  : -1e30f;
            }
        }

        #pragma unroll
        for (int ii = 0; ii < 4; ++ii) {
            float mx = fmaxf(fmaxf(s[ii][0], s[ii][1]), fmaxf(s[ii][2], s[ii][3]));
            mx = fmaxf(mx, __shfl_xor_sync(0xffffffffu, mx, 1));
            mx = fmaxf(mx, __shfl_xor_sync(0xffffffffu, mx, 2));
            mx = fmaxf(mx, __shfl_xor_sync(0xffffffffu, mx, 4));
            mx = fmaxf(mx, __shfl_xor_sync(0xffffffffu, mx, 8));
            const float newm = fmaxf(mrow[ii], mx);
            const float corr = __expf(mrow[ii] - newm);
            mrow[ii] = newm;
            float rs = 0.0f;
            #pragma unroll
            for (int jj = 0; jj < 4; ++jj) {
                const float p = (s[ii][jj] > -1e29f) ? __expf(s[ii][jj] - newm) : 0.0f;
                s[ii][jj] = p;
                rs += p;
            }
            rs += __shfl_xor_sync(0xffffffffu, rs, 1);
            rs += __shfl_xor_sync(0xffffffffu, rs, 2);
            rs += __shfl_xor_sync(0xffffffffu, rs, 4);
            rs += __shfl_xor_sync(0xffffffffu, rs, 8);
            lrow[ii] = lrow[ii] * corr + rs;
            #pragma unroll
            for (int c = 0; c < 4; ++c) o[ii][c] *= corr;
        }

        #pragma unroll
        for (int jj = 0; jj < 4; ++jj)
            #pragma unroll
            for (int ii = 0; ii < 4; ++ii)
                Pt[(tx * 4 + jj) * SMS + ty * 4 + ii] = s[ii][jj];
        __syncthreads();

        #pragma unroll 16
        for (int j = 0; j < 64; ++j) {
            float4 pa = *(const float4*)&Pt[j * SMS + ty * 4];
            float4 vb = *(const float4*)&Vs[j * SMS + tx * 4];
            float pr[4] = {pa.x, pa.y, pa.z, pa.w};
            float vr[4] = {vb.x, vb.y, vb.z, vb.w};
            #pragma unroll
            for (int ii = 0; ii < 4; ++ii)
                #pragma unroll
                for (int c = 0; c < 4; ++c)
                    o[ii][c] = fmaf(pr[ii], vr[c], o[ii][c]);
        }
        __syncthreads();
    }

    #pragma unroll
    for (int ii = 0; ii < 4; ++ii) {
        const float inv = 1.0f / lrow[ii];
        float4 r = make_float4(rna_tf32(o[ii][0] * inv),
                               rna_tf32(o[ii][1] * inv),
                               rna_tf32(o[ii][2] * inv),
                               rna_tf32(o[ii][3] * inv));
        const size_t off = (size_t)(b * S_LEN + i0 + ty * 4 + ii) * D_MODEL
                         + h * DHEAD + tx * 4;
        *(float4*)&g_ao[off] = r;
    }
}

// ---------------------------------------------------------------------------
// Launch
// ---------------------------------------------------------------------------
extern "C" void kernel_launch(void* const* d_in, const int* in_sizes, int n_in,
                              void* d_out, int out_size)
{
    const float* x     = (const float*)d_in[0];
    const float* Wq    = (const float*)d_in[1];
    const float* bq    = (const float*)d_in[2];
    const float* Wk    = (const float*)d_in[3];
    const float* bk    = (const float*)d_in[4];
    const float* Wv    = (const float*)d_in[5];
    const float* bv    = (const float*)d_in[6];
    const float* Wo    = (const float*)d_in[7];
    const float* bo    = (const float*)d_in[8];
    const float* alibi = (const float*)d_in[9];
    float* out = (float*)d_out;

    float *rx, *rwq, *rwk, *rwv, *rwo;
    cudaGetSymbolAddress((void**)&rx,  g_x);
    cudaGetSymbolAddress((void**)&rwq, g_wq);
    cudaGetSymbolAddress((void**)&rwk, g_wk);
    cudaGetSymbolAddress((void**)&rwv, g_wv);
    cudaGetSymbolAddress((void**)&rwo, g_wo);

    cudaFuncSetAttribute(qkv_kernel,
                         cudaFuncAttributeMaxDynamicSharedMemorySize, GEMM_SMEM);
    cudaFuncSetAttribute(oproj_kernel,
                         cudaFuncAttributeMaxDynamicSharedMemorySize, GEMM_SMEM);
    cudaFuncSetAttribute(attn_kernel,
                         cudaFuncAttributeMaxDynamicSharedMemorySize, ATTN_SMEM);

    // tf32-round GEMM inputs (element counts are multiples of 4)
    round_tf32_kernel<<<1024, 256>>>(x,  rx,  MROWS * D_MODEL / 4);
    round_tf32_kernel<<<1024, 256>>>(Wq, rwq, D_MODEL * D_MODEL / 4);
    round_tf32_kernel<<<512,  256>>>(Wk, rwk, KVD * D_MODEL / 4);
    round_tf32_kernel<<<512,  256>>>(Wv, rwv, KVD * D_MODEL / 4);
    round_tf32_kernel<<<1024, 256>>>(Wo, rwo, D_MODEL * D_MODEL / 4);

    qkv_kernel<<<dim3(32, 24), 256, GEMM_SMEM>>>(bq, bk, bv);
    attn_kernel<<<dim3(S_LEN / TQ, NHEADS, BATCH), 256, ATTN_SMEM>>>(alibi);
    oproj_kernel<<<dim3(32, 16), 256, GEMM_SMEM>>>(bo, out);
}

// round 8
// speedup vs baseline: 3.8036x; 1.6581x over previous
#include <cuda_runtime.h>
#include <cuda_bf16.h>
#include <cstdint>

// ---------------------------------------------------------------------------
// Problem constants
// ---------------------------------------------------------------------------
#define S_LEN   2048
#define D_MODEL 2048
#define NHEADS  32
#define NKV     8
#define DHEAD   64
#define WIN     1024
#define BATCH   2
#define MROWS   (BATCH * S_LEN)   // 4096
#define KVD     (NKV * DHEAD)     // 512

// Scratch (device globals — no allocation allowed)
__device__ float g_q [MROWS * D_MODEL];
__device__ float g_k [MROWS * KVD];
__device__ float g_v [MROWS * KVD];
__device__ float g_ao[MROWS * D_MODEL];
// tf32-rounded copies of GEMM inputs
__device__ float g_x [MROWS * D_MODEL];
__device__ float g_wq[D_MODEL * D_MODEL];
__device__ float g_wk[KVD * D_MODEL];
__device__ float g_wv[KVD * D_MODEL];
__device__ float g_wo[D_MODEL * D_MODEL];

// ---------------------------------------------------------------------------
// Helpers
// ---------------------------------------------------------------------------
__device__ __forceinline__ uint32_t smem_to_u32(const void* p) {
    uint32_t a;
    asm("{ .reg .u64 t; cvta.to.shared.u64 t, %1; cvt.u32.u64 %0, t; }"
        : "=r"(a) : "l"(p));
    return a;
}
__device__ __forceinline__ float rna_tf32(float x) {
    uint32_t u;
    asm("cvt.rna.tf32.f32 %0, %1;" : "=r"(u) : "f"(x));
    return __uint_as_float(u);
}

#define CP_ASYNC_CG(dst, src) \
    asm volatile("cp.async.cg.shared.global [%0], [%1], 16;" \
        :: "r"(dst), "l"(src))
#define CP_COMMIT() asm volatile("cp.async.commit_group;" ::: "memory")
#define CP_WAIT(n)  asm volatile("cp.async.wait_group %0;" :: "n"(n) : "memory")

#define LDSM_X4(r0, r1, r2, r3, addr) \
    asm volatile("ldmatrix.sync.aligned.m8n8.x4.shared.b16 {%0,%1,%2,%3}, [%4];" \
        : "=r"(r0), "=r"(r1), "=r"(r2), "=r"(r3) : "r"(addr))

#define MMA_TF32(d, a0, a1, a2, a3, b0, b1) \
    asm volatile("mma.sync.aligned.m16n8k8.row.col.f32.tf32.tf32.f32 " \
        "{%0,%1,%2,%3},{%4,%5,%6,%7},{%8,%9},{%0,%1,%2,%3};" \
        : "+f"((d)[0]), "+f"((d)[1]), "+f"((d)[2]), "+f"((d)[3]) \
        : "r"(a0), "r"(a1), "r"(a2), "r"(a3), "r"(b0), "r"(b1))

// ---------------------------------------------------------------------------
// tf32-rounding pre-pass
// ---------------------------------------------------------------------------
__global__ void round_tf32_kernel(const float* __restrict__ in,
                                  float* __restrict__ out, int n4)
{
    for (int i = blockIdx.x * blockDim.x + threadIdx.x; i < n4;
         i += gridDim.x * blockDim.x) {
        float4 v = ((const float4*)in)[i];
        v.x = rna_tf32(v.x); v.y = rna_tf32(v.y);
        v.z = rna_tf32(v.z); v.w = rna_tf32(v.w);
        ((float4*)out)[i] = v;
    }
}

// ---------------------------------------------------------------------------
// tf32 mma.sync GEMM: C[M,N] = A[M,K] @ W[N,K]^T + bias[N]
// (unchanged from R6 except optional tf32-rounding of outputs)
// ---------------------------------------------------------------------------
#define GSTAGES 4
#define GSTAGE_BYTES 16384
#define GEMM_SMEM (GSTAGES * GSTAGE_BYTES)

__device__ __forceinline__ void gemm_load_stage(
    uint32_t smem_u, const float* __restrict__ A, const float* __restrict__ W,
    int K, int m0, int n0, int t, int tid)
{
    const uint32_t base = smem_u + (t & (GSTAGES - 1)) * GSTAGE_BYTES;
    const int k0 = t * 16;
    #pragma unroll
    for (int i = 0; i < 4; ++i) {
        const int id  = tid + i * 256;
        const int isB = id >> 9;
        const int id2 = id & 511;
        const int row = id2 >> 2;
        const int c   = id2 & 3;
        const float* src = (isB ? W + (size_t)(n0 + row) * K
                                : A + (size_t)(m0 + row) * K) + k0 + c * 4;
        const uint32_t dst = base + (isB ? 8192 : 0) + row * 64
                           + ((c ^ ((row >> 1) & 3)) * 16);
        CP_ASYNC_CG(dst, src);
    }
}

__device__ __forceinline__ void gemm_tile_mma(
    const float* __restrict__ A, const float* __restrict__ W,
    const float* __restrict__ bias, float* __restrict__ C,
    int ldc, int K, int m0, int n0, char* smem, bool round_out)
{
    const uint32_t smem_u = smem_to_u32(smem);
    const int tid    = threadIdx.x;
    const int lane   = tid & 31;
    const int wid    = tid >> 5;
    const int warp_m = wid >> 2;
    const int warp_n = wid & 3;

    int offA[4][2], offB[2][2];
    {
        const int arow_lo = ((lane >> 3) & 1) * 8 + (lane & 7);
        const int ahi     = lane >> 4;
        #pragma unroll
        for (int fm = 0; fm < 4; ++fm) {
            const int row = warp_m * 64 + fm * 16 + arow_lo;
            const int sw  = (row >> 1) & 3;
            #pragma unroll
            for (int ks = 0; ks < 2; ++ks) {
                const int chunk = 2 * ks + ahi;
                offA[fm][ks] = row * 64 + ((chunk ^ sw) & 3) * 16;
            }
        }
        const int brow_lo = ((lane >> 4) & 1) * 8 + (lane & 7);
        const int bhi     = (lane >> 3) & 1;
        #pragma unroll
        for (int p = 0; p < 2; ++p) {
            const int row = warp_n * 32 + p * 16 + brow_lo;
            const int sw  = (row >> 1) & 3;
            #pragma unroll
            for (int ks = 0; ks < 2; ++ks) {
                const int chunk = 2 * ks + bhi;
                offB[p][ks] = row * 64 + ((chunk ^ sw) & 3) * 16;
            }
        }
    }

    float acc[4][4][4];
    #pragma unroll
    for (int i = 0; i < 4; ++i)
        #pragma unroll
        for (int j = 0; j < 4; ++j)
            #pragma unroll
            for (int r = 0; r < 4; ++r) acc[i][j][r] = 0.0f;

    const int T = K >> 4;

    #pragma unroll
    for (int s = 0; s < GSTAGES - 1; ++s) {
        gemm_load_stage(smem_u, A, W, K, m0, n0, s, tid);
        CP_COMMIT();
    }

    for (int t = 0; t < T; ++t) {
        CP_WAIT(GSTAGES - 2);
        __syncthreads();

        if (t + GSTAGES - 1 < T)
            gemm_load_stage(smem_u, A, W, K, m0, n0, t + GSTAGES - 1, tid);
        CP_COMMIT();

        const uint32_t sA = smem_u + (t & (GSTAGES - 1)) * GSTAGE_BYTES;
        const uint32_t sB = sA + 8192;

        #pragma unroll
        for (int ks = 0; ks < 2; ++ks) {
            uint32_t a[4][4], b[2][4];
            #pragma unroll
            for (int fm = 0; fm < 4; ++fm)
                LDSM_X4(a[fm][0], a[fm][1], a[fm][2], a[fm][3],
                        sA + offA[fm][ks]);
            #pragma unroll
            for (int p = 0; p < 2; ++p)
                LDSM_X4(b[p][0], b[p][1], b[p][2], b[p][3],
                        sB + offB[p][ks]);
            #pragma unroll
            for (int fm = 0; fm < 4; ++fm) {
                #pragma unroll
                for (int fn = 0; fn < 4; ++fn) {
                    const int p  = fn >> 1;
                    const int r0 = (fn & 1) * 2;
                    MMA_TF32(acc[fm][fn], a[fm][0], a[fm][1], a[fm][2],
                             a[fm][3], b[p][r0], b[p][r0 + 1]);
                }
            }
        }
    }

    const int trow = lane >> 2;
    const int tcol = (lane & 3) * 2;
    #pragma unroll
    for (int fm = 0; fm < 4; ++fm) {
        const int row = m0 + warp_m * 64 + fm * 16 + trow;
        #pragma unroll
        for (int fn = 0; fn < 4; ++fn) {
            const int col = n0 + warp_n * 32 + fn * 8 + tcol;
            const float2 bb = *(const float2*)(bias + col);
            float2 lo = make_float2(acc[fm][fn][0] + bb.x,
                                    acc[fm][fn][1] + bb.y);
            float2 hi = make_float2(acc[fm][fn][2] + bb.x,
                                    acc[fm][fn][3] + bb.y);
            if (round_out) {
                lo.x = rna_tf32(lo.x); lo.y = rna_tf32(lo.y);
                hi.x = rna_tf32(hi.x); hi.y = rna_tf32(hi.y);
            }
            *(float2*)(C + (size_t)row * ldc + col)       = lo;
            *(float2*)(C + (size_t)(row + 8) * ldc + col) = hi;
        }
    }
}

__global__ __launch_bounds__(256, 2)
void qkv_kernel(const float* __restrict__ bq, const float* __restrict__ bk,
                const float* __restrict__ bv)
{
    extern __shared__ __align__(128) char smem[];
    const int y = blockIdx.y;
    const float *W, *bias;
    float* C;
    int ldc, n0;
    if (y < 16)      { W = g_wq; bias = bq; C = g_q; ldc = D_MODEL; n0 = y * 128; }
    else if (y < 20) { W = g_wk; bias = bk; C = g_k; ldc = KVD;     n0 = (y - 16) * 128; }
    else             { W = g_wv; bias = bv; C = g_v; ldc = KVD;     n0 = (y - 20) * 128; }
    gemm_tile_mma(g_x, W, bias, C, ldc, D_MODEL, blockIdx.x * 128, n0, smem, true);
}

__global__ __launch_bounds__(256, 2)
void oproj_kernel(const float* __restrict__ bo, float* __restrict__ out)
{
    extern __shared__ __align__(128) char smem[];
    gemm_tile_mma(g_ao, g_wo, bo, out, D_MODEL, D_MODEL,
                  blockIdx.x * 128, blockIdx.y * 128, smem, false);
}

// ---------------------------------------------------------------------------
// Flash attention, tf32 mma.sync version.
// CTA = 64 q-rows x head x batch. 256 threads = 8 warps in 2(m) x 4(n) grid.
// S phase:  warp (wm,wn) computes S[wm*32 +: 32][wn*16 +: 16] via m16n8k8.
// PV phase: warp (wm,wn) computes O[wm*32 +: 32][wn*16 +: 16 of dh].
// Q frags persistent in registers; K/V double-buffered via cp.async;
// P staged in smem; online softmax with cross-warp smem reduction.
// ---------------------------------------------------------------------------
#define AT_KST 68
#define AT_VST 72
#define AT_PST 68
#define AT_OFF_KS 0
#define AT_OFF_VS (2 * 64 * AT_KST)                 // 8704
#define AT_OFF_PS (AT_OFF_VS + 2 * 64 * AT_VST)     // 17920
#define AT_OFF_RM (AT_OFF_PS + 64 * AT_PST)         // 22272
#define AT_OFF_RS (AT_OFF_RM + 256)                 // 22528
#define ATTN_SMEM ((AT_OFF_RS + 256) * 4)           // 91136 bytes

__device__ __forceinline__ void attn_load_kv(
    uint32_t smem_u, int bufsel, int b, int hkv, int j0, int tid)
{
    const size_t kvoff = (size_t)(b * S_LEN + j0) * KVD + hkv * DHEAD;
    #pragma unroll
    for (int p = 0; p < 4; ++p) {
        const int cidx = tid + p * 256;
        const int row = cidx >> 4;
        const int c   = cidx & 15;
        const float* ks = g_k + kvoff + (size_t)row * KVD + c * 4;
        const float* vs = g_v + kvoff + (size_t)row * KVD + c * 4;
        const uint32_t kd = smem_u +
            (AT_OFF_KS + bufsel * 64 * AT_KST + row * AT_KST + c * 4) * 4;
        const uint32_t vd = smem_u +
            (AT_OFF_VS + bufsel * 64 * AT_VST + row * AT_VST + c * 4) * 4;
        CP_ASYNC_CG(kd, ks);
        CP_ASYNC_CG(vd, vs);
    }
}

__global__ __launch_bounds__(256, 1)
void attn_kernel(const float* __restrict__ alibi)
{
    extern __shared__ __align__(16) float sm[];
    float* Ps = sm + AT_OFF_PS;
    float* Rm = sm + AT_OFF_RM;
    float* Rs = sm + AT_OFF_RS;
    const uint32_t smem_u = smem_to_u32(sm);

    const int tid  = threadIdx.x;
    const int lane = tid & 31;
    const int wid  = tid >> 5;
    const int wm   = wid >> 2;      // 0..1: 32-row half
    const int wn   = wid & 3;       // 0..3: 16-col slice
    const int gid  = lane >> 2;     // 0..7
    const int tig  = lane & 3;      // 0..3

    const int i0 = blockIdx.x * 64;
    const int h  = blockIdx.y;
    const int b  = blockIdx.z;
    const int hkv = h >> 2;
    const float slope = alibi[h];

    const int jt_lo = max(0, i0 - (WIN - 1)) >> 6;
    const int jt_hi = i0 >> 6;

    // prefetch first KV tile into buffer 0
    attn_load_kv(smem_u, 0, b, hkv, jt_lo << 6, tid);
    CP_COMMIT();

    // stage Q into Ps region (reused later for P), then load persistent frags
    {
        const size_t qoff = (size_t)(b * S_LEN + i0) * D_MODEL + h * DHEAD;
        #pragma unroll
        for (int p = 0; p < 4; ++p) {
            const int cidx = tid + p * 256;
            const int row = cidx >> 4, c = cidx & 15;
            float4 v = *(const float4*)(g_q + qoff + (size_t)row * D_MODEL + c * 4);
            *(float4*)(Ps + row * AT_PST + c * 4) = v;
        }
    }
    __syncthreads();

    uint32_t qf[2][8][4];
    #pragma unroll
    for (int mf = 0; mf < 2; ++mf) {
        const int r = wm * 32 + mf * 16 + gid;
        #pragma unroll
        for (int ks = 0; ks < 8; ++ks) {
            qf[mf][ks][0] = __float_as_uint(Ps[r       * AT_PST + ks * 8 + tig]);
            qf[mf][ks][1] = __float_as_uint(Ps[(r + 8) * AT_PST + ks * 8 + tig]);
            qf[mf][ks][2] = __float_as_uint(Ps[r       * AT_PST + ks * 8 + tig + 4]);
            qf[mf][ks][3] = __float_as_uint(Ps[(r + 8) * AT_PST + ks * 8 + tig + 4]);
        }
    }

    float o[2][2][4];
    #pragma unroll
    for (int mf = 0; mf < 2; ++mf)
        #pragma unroll
        for (int nf = 0; nf < 2; ++nf)
            #pragma unroll
            for (int c = 0; c < 4; ++c) o[mf][nf][c] = 0.0f;
    float m_[2][2] = {{-1e30f, -1e30f}, {-1e30f, -1e30f}};
    float l_[2][2] = {{0.0f, 0.0f}, {0.0f, 0.0f}};

    int bufsel = 0;
    for (int jt = jt_lo; jt <= jt_hi; ++jt, bufsel ^= 1) {
        CP_WAIT(0);
        __syncthreads();    // KV(t) ready; also guards Ps reuse vs prior PV

        if (jt < jt_hi) {
            attn_load_kv(smem_u, bufsel ^ 1, b, hkv, (jt + 1) << 6, tid);
            CP_COMMIT();
        }

        const int j0 = jt << 6;
        const float* Kb = sm + AT_OFF_KS + bufsel * 64 * AT_KST;
        const float* Vb = sm + AT_OFF_VS + bufsel * 64 * AT_VST;

        // ---- S = Q @ K^T ----
        float s[2][2][4];
        #pragma unroll
        for (int mf = 0; mf < 2; ++mf)
            #pragma unroll
            for (int nf = 0; nf < 2; ++nf)
                #pragma unroll
                for (int c = 0; c < 4; ++c) s[mf][nf][c] = 0.0f;

        #pragma unroll
        for (int ks = 0; ks < 8; ++ks) {
            uint32_t bfr[2][2];
            #pragma unroll
            for (int nf = 0; nf < 2; ++nf) {
                const int jr = wn * 16 + nf * 8 + gid;
                bfr[nf][0] = __float_as_uint(Kb[jr * AT_KST + ks * 8 + tig]);
                bfr[nf][1] = __float_as_uint(Kb[jr * AT_KST + ks * 8 + tig + 4]);
            }
            #pragma unroll
            for (int mf = 0; mf < 2; ++mf)
                #pragma unroll
                for (int nf = 0; nf < 2; ++nf)
                    MMA_TF32(s[mf][nf], qf[mf][ks][0], qf[mf][ks][1],
                             qf[mf][ks][2], qf[mf][ks][3],
                             bfr[nf][0], bfr[nf][1]);
        }

        // ---- scale + ALiBi + sliding-window mask ----
        const int di = i0 - j0;
        const bool fullv = (di >= 64 && di <= 960);
        #pragma unroll
        for (int mf = 0; mf < 2; ++mf)
            #pragma unroll
            for (int nf = 0; nf < 2; ++nf)
                #pragma unroll
                for (int c = 0; c < 4; ++c) {
                    const int dlt = di + (wm * 32 + mf * 16 + ((c & 2) << 2) + gid)
                                  - (wn * 16 + nf * 8 + 2 * tig + (c & 1));
                    const bool valid = fullv || ((unsigned)dlt < WIN);
                    const float sv = fmaf(s[mf][nf][c], 0.125f,
                                          -slope * (float)dlt);
                    s[mf][nf][c] = valid ? sv : -1e30f;
                }

        // ---- row max: in-thread + shfl (tig) + cross-warp (wn) via smem ----
        float pmax[2][2];
        #pragma unroll
        for (int mf = 0; mf < 2; ++mf)
            #pragma unroll
            for (int hh = 0; hh < 2; ++hh) {
                float v = fmaxf(fmaxf(s[mf][0][hh * 2], s[mf][0][hh * 2 + 1]),
                                fmaxf(s[mf][1][hh * 2], s[mf][1][hh * 2 + 1]));
                v = fmaxf(v, __shfl_xor_sync(0xffffffffu, v, 1));
                v = fmaxf(v, __shfl_xor_sync(0xffffffffu, v, 2));
                pmax[mf][hh] = v;
            }
        if (tig == 0) {
            #pragma unroll
            for (int mf = 0; mf < 2; ++mf)
                #pragma unroll
                for (int hh = 0; hh < 2; ++hh)
                    Rm[wm * 128 + (mf * 16 + hh * 8 + gid) * 4 + wn] = pmax[mf][hh];
        }
        __syncthreads();

        float corr[2][2], psum[2][2];
        #pragma unroll
        for (int mf = 0; mf < 2; ++mf)
            #pragma unroll
            for (int hh = 0; hh < 2; ++hh) {
                float4 rv = *(const float4*)&Rm[wm * 128 + (mf * 16 + hh * 8 + gid) * 4];
                const float rmax = fmaxf(fmaxf(rv.x, rv.y), fmaxf(rv.z, rv.w));
                const float nm = fmaxf(m_[mf][hh], rmax);
                corr[mf][hh] = __expf(m_[mf][hh] - nm);
                m_[mf][hh] = nm;
                psum[mf][hh] = 0.0f;
            }

        // ---- exp + partial sums + P store (tf32-rounded) ----
        #pragma unroll
        for (int mf = 0; mf < 2; ++mf)
            #pragma unroll
            for (int nf = 0; nf < 2; ++nf)
                #pragma unroll
                for (int c = 0; c < 4; ++c) {
                    const int hh = c >> 1;
                    const float p = __expf(s[mf][nf][c] - m_[mf][hh]);
                    s[mf][nf][c] = p;
                    psum[mf][hh] += p;
                }
        #pragma unroll
        for (int mf = 0; mf < 2; ++mf)
            #pragma unroll
            for (int hh = 0; hh < 2; ++hh) {
                float v = psum[mf][hh];
                v += __shfl_xor_sync(0xffffffffu, v, 1);
                v += __shfl_xor_sync(0xffffffffu, v, 2);
                psum[mf][hh] = v;
            }
        if (tig == 0) {
            #pragma unroll
            for (int mf = 0; mf < 2; ++mf)
                #pragma unroll
                for (int hh = 0; hh < 2; ++hh)
                    Rs[wm * 128 + (mf * 16 + hh * 8 + gid) * 4 + wn] = psum[mf][hh];
        }
        #pragma unroll
        for (int mf = 0; mf < 2; ++mf)
            #pragma unroll
            for (int nf = 0; nf < 2; ++nf)
                #pragma unroll
                for (int hh = 0; hh < 2; ++hh) {
                    const int row = wm * 32 + mf * 16 + hh * 8 + gid;
                    float2 pv = make_float2(rna_tf32(s[mf][nf][hh * 2]),
                                            rna_tf32(s[mf][nf][hh * 2 + 1]));
                    *(float2*)&Ps[row * AT_PST + wn * 16 + nf * 8 + 2 * tig] = pv;
                }
        __syncthreads();

        // ---- l update, O rescale, O += P @ V ----
        #pragma unroll
        for (int mf = 0; mf < 2; ++mf)
            #pragma unroll
            for (int hh = 0; hh < 2; ++hh) {
                float4 rv = *(const float4*)&Rs[wm * 128 + (mf * 16 + hh * 8 + gid) * 4];
                l_[mf][hh] = l_[mf][hh] * corr[mf][hh]
                           + (rv.x + rv.y + rv.z + rv.w);
            }
        #pragma unroll
        for (int mf = 0; mf < 2; ++mf)
            #pragma unroll
            for (int nf = 0; nf < 2; ++nf)
                #pragma unroll
                for (int c = 0; c < 4; ++c)
                    o[mf][nf][c] *= corr[mf][c >> 1];

        #pragma unroll
        for (int ks = 0; ks < 8; ++ks) {
            uint32_t af[2][4], bfr[2][2];
            #pragma unroll
            for (int mf = 0; mf < 2; ++mf) {
                const int r = wm * 32 + mf * 16 + gid;
                af[mf][0] = __float_as_uint(Ps[r       * AT_PST + ks * 8 + tig]);
                af[mf][1] = __float_as_uint(Ps[(r + 8) * AT_PST + ks * 8 + tig]);
                af[mf][2] = __float_as_uint(Ps[r       * AT_PST + ks * 8 + tig + 4]);
                af[mf][3] = __float_as_uint(Ps[(r + 8) * AT_PST + ks * 8 + tig + 4]);
            }
            #pragma unroll
            for (int nf = 0; nf < 2; ++nf) {
                const int dc = wn * 16 + nf * 8 + gid;
                bfr[nf][0] = __float_as_uint(Vb[(ks * 8 + tig)     * AT_VST + dc]);
                bfr[nf][1] = __float_as_uint(Vb[(ks * 8 + tig + 4) * AT_VST + dc]);
            }
            #pragma unroll
            for (int mf = 0; mf < 2; ++mf)
                #pragma unroll
                for (int nf = 0; nf < 2; ++nf)
                    MMA_TF32(o[mf][nf], af[mf][0], af[mf][1], af[mf][2],
                             af[mf][3], bfr[nf][0], bfr[nf][1]);
        }
    }

    // ---- normalize + write (tf32-rounded for the O-projection) ----
    #pragma unroll
    for (int mf = 0; mf < 2; ++mf)
        #pragma unroll
        for (int hh = 0; hh < 2; ++hh) {
            const float inv = 1.0f / l_[mf][hh];
            const size_t row = (size_t)(b * S_LEN + i0 + wm * 32 + mf * 16
                                        + hh * 8 + gid);
            #pragma unroll
            for (int nf = 0; nf < 2; ++nf) {
                const int col = h * DHEAD + wn * 16 + nf * 8 + 2 * tig;
                float2 ov = make_float2(rna_tf32(o[mf][nf][hh * 2] * inv),
                                        rna_tf32(o[mf][nf][hh * 2 + 1] * inv));
                *(float2*)&g_ao[row * D_MODEL + col] = ov;
            }
        }
}

// ---------------------------------------------------------------------------
// Launch
// ---------------------------------------------------------------------------
extern "C" void kernel_launch(void* const* d_in, const int* in_sizes, int n_in,
                              void* d_out, int out_size)
{
    const float* x     = (const float*)d_in[0];
    const float* Wq    = (const float*)d_in[1];
    const float* bq    = (const float*)d_in[2];
    const float* Wk    = (const float*)d_in[3];
    const float* bk    = (const float*)d_in[4];
    const float* Wv    = (const float*)d_in[5];
    const float* bv    = (const float*)d_in[6];
    const float* Wo    = (const float*)d_in[7];
    const float* bo    = (const float*)d_in[8];
    const float* alibi = (const float*)d_in[9];
    float* out = (float*)d_out;

    float *rx, *rwq, *rwk, *rwv, *rwo;
    cudaGetSymbolAddress((void**)&rx,  g_x);
    cudaGetSymbolAddress((void**)&rwq, g_wq);
    cudaGetSymbolAddress((void**)&rwk, g_wk);
    cudaGetSymbolAddress((void**)&rwv, g_wv);
    cudaGetSymbolAddress((void**)&rwo, g_wo);

    cudaFuncSetAttribute(qkv_kernel,
                         cudaFuncAttributeMaxDynamicSharedMemorySize, GEMM_SMEM);
    cudaFuncSetAttribute(oproj_kernel,
                         cudaFuncAttributeMaxDynamicSharedMemorySize, GEMM_SMEM);
    cudaFuncSetAttribute(attn_kernel,
                         cudaFuncAttributeMaxDynamicSharedMemorySize, ATTN_SMEM);

    round_tf32_kernel<<<1024, 256>>>(x,  rx,  MROWS * D_MODEL / 4);
    round_tf32_kernel<<<1024, 256>>>(Wq, rwq, D_MODEL * D_MODEL / 4);
    round_tf32_kernel<<<512,  256>>>(Wk, rwk, KVD * D_MODEL / 4);
    round_tf32_kernel<<<512,  256>>>(Wv, rwv, KVD * D_MODEL / 4);
    round_tf32_kernel<<<1024, 256>>>(Wo, rwo, D_MODEL * D_MODEL / 4);

    qkv_kernel<<<dim3(32, 24), 256, GEMM_SMEM>>>(bq, bk, bv);
    attn_kernel<<<dim3(S_LEN / 64, NHEADS, BATCH), 256, ATTN_SMEM>>>(alibi);
    oproj_kernel<<<dim3(32, 16), 256, GEMM_SMEM>>>(bo, out);
}

// round 9
// speedup vs baseline: 7.4968x; 1.9710x over previous
#include <cuda_runtime.h>
#include <cuda_fp16.h>
#include <cstdint>

// ---------------------------------------------------------------------------
// Problem constants
// ---------------------------------------------------------------------------
#define S_LEN   2048
#define D_MODEL 2048
#define NHEADS  32
#define NKV     8
#define DHEAD   64
#define WIN     1024
#define BATCH   2
#define MROWS   (BATCH * S_LEN)   // 4096
#define KVD     (NKV * DHEAD)     // 512

// Scratch (device globals — no allocation allowed). All fp16 now.
__device__ __half g_q [MROWS * D_MODEL];
__device__ __half g_k [MROWS * KVD];
__device__ __half g_v [MROWS * KVD];
__device__ __half g_ao[MROWS * D_MODEL];
// fp16 copies of GEMM inputs
__device__ __half g_x [MROWS * D_MODEL];
__device__ __half g_wq[D_MODEL * D_MODEL];
__device__ __half g_wk[KVD * D_MODEL];
__device__ __half g_wv[KVD * D_MODEL];
__device__ __half g_wo[D_MODEL * D_MODEL];

// ---------------------------------------------------------------------------
// Helpers
// ---------------------------------------------------------------------------
__device__ __forceinline__ uint32_t smem_to_u32(const void* p) {
    uint32_t a;
    asm("{ .reg .u64 t; cvta.to.shared.u64 t, %1; cvt.u32.u64 %0, t; }"
        : "=r"(a) : "l"(p));
    return a;
}

#define CP_ASYNC_CG(dst, src) \
    asm volatile("cp.async.cg.shared.global [%0], [%1], 16;" \
        :: "r"(dst), "l"(src))
#define CP_COMMIT() asm volatile("cp.async.commit_group;" ::: "memory")
#define CP_WAIT(n)  asm volatile("cp.async.wait_group %0;" :: "n"(n) : "memory")

#define LDSM_X4(r0, r1, r2, r3, addr) \
    asm volatile("ldmatrix.sync.aligned.m8n8.x4.shared.b16 {%0,%1,%2,%3}, [%4];" \
        : "=r"(r0), "=r"(r1), "=r"(r2), "=r"(r3) : "r"(addr))
#define LDSM_X4_T(r0, r1, r2, r3, addr) \
    asm volatile("ldmatrix.sync.aligned.m8n8.x4.trans.shared.b16 {%0,%1,%2,%3}, [%4];" \
        : "=r"(r0), "=r"(r1), "=r"(r2), "=r"(r3) : "r"(addr))

#define MMA_F16(d, a0, a1, a2, a3, b0, b1) \
    asm volatile("mma.sync.aligned.m16n8k16.row.col.f32.f16.f16.f32 " \
        "{%0,%1,%2,%3},{%4,%5,%6,%7},{%8,%9},{%0,%1,%2,%3};" \
        : "+f"((d)[0]), "+f"((d)[1]), "+f"((d)[2]), "+f"((d)[3]) \
        : "r"(a0), "r"(a1), "r"(a2), "r"(a3), "r"(b0), "r"(b1))

// ---------------------------------------------------------------------------
// fp32 -> fp16 conversion pre-pass
// ---------------------------------------------------------------------------
__global__ void to_half_kernel(const float* __restrict__ in,
                               __half* __restrict__ out, int n4)
{
    for (int i = blockIdx.x * blockDim.x + threadIdx.x; i < n4;
         i += gridDim.x * blockDim.x) {
        float4 v = ((const float4*)in)[i];
        __half2 h0 = __floats2half2_rn(v.x, v.y);
        __half2 h1 = __floats2half2_rn(v.z, v.w);
        uint2 u;
        u.x = *(uint32_t*)&h0;
        u.y = *(uint32_t*)&h1;
        ((uint2*)out)[i] = u;
    }
}

// ---------------------------------------------------------------------------
// fp16 mma.sync GEMM: C[M,N] = A[M,K] @ W[N,K]^T + bias[N]
// CTA tile 128x128, BK=64, 3-stage cp.async, 8 warps (2m x 4n),
// warp tile 64x32. smem stage rows = 64 halves = 128B, XOR-swizzled chunks.
// ---------------------------------------------------------------------------
#define GBK 64
#define GSTAGE_BYTES 32768               // 16KB A + 16KB B
#define GEMM_SMEM (3 * GSTAGE_BYTES)     // 96KB

__device__ __forceinline__ void gemm_load_stage(
    uint32_t smem_u, const __half* __restrict__ A, const __half* __restrict__ W,
    int K, int m0, int n0, int t, int slot, int tid)
{
    const uint32_t base = smem_u + slot * GSTAGE_BYTES;
    const int k0 = t * GBK;
    #pragma unroll
    for (int i = 0; i < 4; ++i) {       // A: 128 rows x 8 chunks
        const int id  = tid + i * 256;
        const int row = id >> 3;
        const int c   = id & 7;
        const __half* src = A + (size_t)(m0 + row) * K + k0 + c * 8;
        const uint32_t dst = base + row * 128 + ((c ^ (row & 7)) * 16);
        CP_ASYNC_CG(dst, src);
    }
    #pragma unroll
    for (int i = 0; i < 4; ++i) {       // B
        const int id  = tid + i * 256;
        const int row = id >> 3;
        const int c   = id & 7;
        const __half* src = W + (size_t)(n0 + row) * K + k0 + c * 8;
        const uint32_t dst = base + 16384 + row * 128 + ((c ^ (row & 7)) * 16);
        CP_ASYNC_CG(dst, src);
    }
}

template <bool HALF_OUT>
__device__ __forceinline__ void gemm_tile(
    const __half* __restrict__ A, const __half* __restrict__ W,
    const float* __restrict__ bias, void* __restrict__ Cout,
    int ldc, int K, int m0, int n0, char* smem)
{
    const uint32_t smem_u = smem_to_u32(smem);
    const int tid    = threadIdx.x;
    const int lane   = tid & 31;
    const int wid    = tid >> 5;
    const int warp_m = wid >> 2;    // 0..1 -> 64 rows
    const int warp_n = wid & 3;     // 0..3 -> 32 cols
    const int gid    = lane >> 2;
    const int tig    = lane & 3;

    // ldmatrix offsets (bytes within a stage half: A rows 128B)
    int offA[4][4], offB[2][4];
    {
        const int arow_lo = ((lane >> 3) & 1) * 8 + (lane & 7);
        const int ahi     = lane >> 4;              // chunk +0/+1
        #pragma unroll
        for (int fm = 0; fm < 4; ++fm) {
            const int row = warp_m * 64 + fm * 16 + arow_lo;
            #pragma unroll
            for (int ks = 0; ks < 4; ++ks) {
                const int chunk = 2 * ks + ahi;
                offA[fm][ks] = row * 128 + ((chunk ^ (row & 7)) * 16);
            }
        }
        const int brow_lo = ((lane >> 4) & 1) * 8 + (lane & 7);
        const int bhi     = (lane >> 3) & 1;
        #pragma unroll
        for (int p = 0; p < 2; ++p) {
            const int row = warp_n * 32 + p * 16 + brow_lo;
            #pragma unroll
            for (int ks = 0; ks < 4; ++ks) {
                const int chunk = 2 * ks + bhi;
                offB[p][ks] = row * 128 + ((chunk ^ (row & 7)) * 16);
            }
        }
    }

    float acc[4][4][4];
    #pragma unroll
    for (int i = 0; i < 4; ++i)
        #pragma unroll
        for (int j = 0; j < 4; ++j)
            #pragma unroll
            for (int r = 0; r < 4; ++r) acc[i][j][r] = 0.0f;

    const int T = K / GBK;     // 32

    gemm_load_stage(smem_u, A, W, K, m0, n0, 0, 0, tid);
    CP_COMMIT();
    gemm_load_stage(smem_u, A, W, K, m0, n0, 1, 1, tid);
    CP_COMMIT();

    int slot = 0, nslot = 2;
    for (int t = 0; t < T; ++t) {
        CP_WAIT(1);
        __syncthreads();

        if (t + 2 < T)
            gemm_load_stage(smem_u, A, W, K, m0, n0, t + 2, nslot, tid);
        CP_COMMIT();

        const uint32_t sA = smem_u + slot * GSTAGE_BYTES;
        const uint32_t sB = sA + 16384;

        #pragma unroll
        for (int ks = 0; ks < 4; ++ks) {
            uint32_t a[4][4], b[2][4];
            #pragma unroll
            for (int fm = 0; fm < 4; ++fm)
                LDSM_X4(a[fm][0], a[fm][1], a[fm][2], a[fm][3],
                        sA + offA[fm][ks]);
            #pragma unroll
            for (int p = 0; p < 2; ++p)
                LDSM_X4(b[p][0], b[p][1], b[p][2], b[p][3],
                        sB + offB[p][ks]);
            #pragma unroll
            for (int fm = 0; fm < 4; ++fm) {
                #pragma unroll
                for (int fn = 0; fn < 4; ++fn) {
                    const int p  = fn >> 1;
                    const int r0 = (fn & 1) * 2;
                    MMA_F16(acc[fm][fn], a[fm][0], a[fm][1], a[fm][2],
                            a[fm][3], b[p][r0], b[p][r0 + 1]);
                }
            }
        }
        slot = (slot == 2) ? 0 : slot + 1;
        nslot = (nslot == 2) ? 0 : nslot + 1;
    }

    // epilogue
    #pragma unroll
    for (int fm = 0; fm < 4; ++fm) {
        const int row = m0 + warp_m * 64 + fm * 16 + gid;
        #pragma unroll
        for (int fn = 0; fn < 4; ++fn) {
            const int col = n0 + warp_n * 32 + fn * 8 + 2 * tig;
            const float2 bb = *(const float2*)(bias + col);
            const float c0 = acc[fm][fn][0] + bb.x;
            const float c1 = acc[fm][fn][1] + bb.y;
            const float c2 = acc[fm][fn][2] + bb.x;
            const float c3 = acc[fm][fn][3] + bb.y;
            if (HALF_OUT) {
                __half* C = (__half*)Cout;
                *(half2*)(C + (size_t)row * ldc + col) = __floats2half2_rn(c0, c1);
                *(half2*)(C + (size_t)(row + 8) * ldc + col) = __floats2half2_rn(c2, c3);
            } else {
                float* C = (float*)Cout;
                *(float2*)(C + (size_t)row * ldc + col)       = make_float2(c0, c1);
                *(float2*)(C + (size_t)(row + 8) * ldc + col) = make_float2(c2, c3);
            }
        }
    }
}

__global__ __launch_bounds__(256, 2)
void qkv_kernel(const float* __restrict__ bq, const float* __restrict__ bk,
                const float* __restrict__ bv)
{
    extern __shared__ __align__(128) char smem[];
    const int y = blockIdx.y;
    const __half *W;
    const float* bias;
    __half* C;
    int ldc, n0;
    if (y < 16)      { W = g_wq; bias = bq; C = g_q; ldc = D_MODEL; n0 = y * 128; }
    else if (y < 20) { W = g_wk; bias = bk; C = g_k; ldc = KVD;     n0 = (y - 16) * 128; }
    else             { W = g_wv; bias = bv; C = g_v; ldc = KVD;     n0 = (y - 20) * 128; }
    gemm_tile<true>(g_x, W, bias, C, ldc, D_MODEL, blockIdx.x * 128, n0, smem);
}

__global__ __launch_bounds__(256, 2)
void oproj_kernel(const float* __restrict__ bo, float* __restrict__ out)
{
    extern __shared__ __align__(128) char smem[];
    gemm_tile<false>(g_ao, g_wo, bo, out, D_MODEL, D_MODEL,
                     blockIdx.x * 128, blockIdx.y * 128, smem);
}

// ---------------------------------------------------------------------------
// Flash attention, fp16 mma m16n8k16.
// CTA = 64 q-rows x head x batch. 8 warps in 2(m) x 4(n).
// Q frags persistent; K via ldmatrix (B operand), V via ldmatrix.trans;
// P staged in smem as half2. Online softmax in fp32 with cross-warp smem
// reduction. smem tiles use 72-half stride (conflict-free by padding).
// ---------------------------------------------------------------------------
#define AST 72                       // halves per row
#define AB_K  0                      // 2 bufs K: 2*64*72*2 = 18432 B
#define AB_V  18432                  // 2 bufs V
#define AB_P  36864                  // P / Q staging: 9216 B
#define AB_RM 46080                  // 256 floats
#define AB_RS 47104                  // 256 floats
#define ATTN_SMEM 48128

__device__ __forceinline__ void attn_load_kv(
    uint32_t smem_u, int buf, int b, int hkv, int j0, int tid)
{
    const size_t kvoff = (size_t)(b * S_LEN + j0) * KVD + hkv * DHEAD;
    #pragma unroll
    for (int p = 0; p < 2; ++p) {
        const int id  = tid + p * 256;
        const int row = id >> 3;
        const int c   = id & 7;
        const __half* ks = g_k + kvoff + (size_t)row * KVD + c * 8;
        const __half* vs = g_v + kvoff + (size_t)row * KVD + c * 8;
        const uint32_t kd = smem_u + AB_K + buf * 9216 + row * 144 + c * 16;
        const uint32_t vd = smem_u + AB_V + buf * 9216 + row * 144 + c * 16;
        CP_ASYNC_CG(kd, ks);
        CP_ASYNC_CG(vd, vs);
    }
}

__global__ __launch_bounds__(256, 2)
void attn_kernel(const float* __restrict__ alibi)
{
    extern __shared__ __align__(16) char smc[];
    const uint32_t smem_u = smem_to_u32(smc);
    __half* Ps = (__half*)(smc + AB_P);
    float*  Rm = (float*)(smc + AB_RM);
    float*  Rs = (float*)(smc + AB_RS);

    const int tid  = threadIdx.x;
    const int lane = tid & 31;
    const int wid  = tid >> 5;
    const int wm   = wid >> 2;      // 0..1: 32-row half
    const int wn   = wid & 3;       // 0..3: 16-col slice
    const int gid  = lane >> 2;
    const int tig  = lane & 3;

    const int i0 = blockIdx.x * 64;
    const int h  = blockIdx.y;
    const int b  = blockIdx.z;
    const int hkv = h >> 2;
    const float slope = alibi[h];

    const int jt_lo = max(0, i0 - (WIN - 1)) >> 6;
    const int jt_hi = i0 >> 6;

    // ldmatrix lane-derived offsets
    const int arow_lo = ((lane >> 3) & 1) * 8 + (lane & 7);
    const int ahi     = lane >> 4;
    const int brow_lo = ((lane >> 4) & 1) * 8 + (lane & 7);
    const int bhi     = (lane >> 3) & 1;
    const int vrow_lo = ((lane >> 3) & 1) * 8 + (lane & 7);
    const int vhi     = lane >> 4;

    // prefetch KV tile 0 + stage Q into Ps
    attn_load_kv(smem_u, 0, b, hkv, jt_lo << 6, tid);
    {
        const size_t qoff = (size_t)(b * S_LEN + i0) * D_MODEL + h * DHEAD;
        #pragma unroll
        for (int p = 0; p < 2; ++p) {
            const int id  = tid + p * 256;
            const int row = id >> 3;
            const int c   = id & 7;
            const __half* src = g_q + qoff + (size_t)row * D_MODEL + c * 8;
            CP_ASYNC_CG(smem_u + AB_P + row * 144 + c * 16, src);
        }
    }
    CP_COMMIT();
    CP_WAIT(0);
    __syncthreads();

    // persistent Q fragments
    uint32_t qf[2][4][4];
    #pragma unroll
    for (int mf = 0; mf < 2; ++mf) {
        const int row = wm * 32 + mf * 16 + arow_lo;
        #pragma unroll
        for (int ks = 0; ks < 4; ++ks) {
            const uint32_t ad = smem_u + AB_P + row * 144 + (2 * ks + ahi) * 16;
            LDSM_X4(qf[mf][ks][0], qf[mf][ks][1], qf[mf][ks][2], qf[mf][ks][3], ad);
        }
    }

    float o[2][2][4];
    #pragma unroll
    for (int mf = 0; mf < 2; ++mf)
        #pragma unroll
        for (int nf = 0; nf < 2; ++nf)
            #pragma unroll
            for (int c = 0; c < 4; ++c) o[mf][nf][c] = 0.0f;
    float m_[2][2] = {{-1e30f, -1e30f}, {-1e30f, -1e30f}};
    float l_[2][2] = {{0.0f, 0.0f}, {0.0f, 0.0f}};

    int buf = 0;
    for (int jt = jt_lo; jt <= jt_hi; ++jt, buf ^= 1) {
        CP_WAIT(0);
        __syncthreads();

        if (jt < jt_hi) {
            attn_load_kv(smem_u, buf ^ 1, b, hkv, (jt + 1) << 6, tid);
            CP_COMMIT();
        }

        const int j0 = jt << 6;
        const uint32_t Kb = smem_u + AB_K + buf * 9216;
        const uint32_t Vb = smem_u + AB_V + buf * 9216;

        // ---- S = Q @ K^T ----
        float s[2][2][4];
        #pragma unroll
        for (int mf = 0; mf < 2; ++mf)
            #pragma unroll
            for (int nf = 0; nf < 2; ++nf)
                #pragma unroll
                for (int c = 0; c < 4; ++c) s[mf][nf][c] = 0.0f;

        #pragma unroll
        for (int ks = 0; ks < 4; ++ks) {
            uint32_t kb[4];
            const int row = wn * 16 + brow_lo;
            LDSM_X4(kb[0], kb[1], kb[2], kb[3],
                    Kb + row * 144 + (2 * ks + bhi) * 16);
            #pragma unroll
            for (int mf = 0; mf < 2; ++mf) {
                MMA_F16(s[mf][0], qf[mf][ks][0], qf[mf][ks][1],
                        qf[mf][ks][2], qf[mf][ks][3], kb[0], kb[1]);
                MMA_F16(s[mf][1], qf[mf][ks][0], qf[mf][ks][1],
                        qf[mf][ks][2], qf[mf][ks][3], kb[2], kb[3]);
            }
        }

        // ---- scale + ALiBi + sliding-window mask ----
        const int di = i0 - j0;
        const bool fullv = (di >= 64 && di <= 960);
        #pragma unroll
        for (int mf = 0; mf < 2; ++mf)
            #pragma unroll
            for (int nf = 0; nf < 2; ++nf)
                #pragma unroll
                for (int c = 0; c < 4; ++c) {
                    const int dlt = di + (wm * 32 + mf * 16 + ((c & 2) << 2) + gid)
                                  - (wn * 16 + nf * 8 + 2 * tig + (c & 1));
                    const bool valid = fullv || ((unsigned)dlt < WIN);
                    const float sv = fmaf(s[mf][nf][c], 0.125f,
                                          -slope * (float)dlt);
                    s[mf][nf][c] = valid ? sv : -1e30f;
                }

        // ---- row max (thread + shfl + cross-warp smem) ----
        float pmax[2][2];
        #pragma unroll
        for (int mf = 0; mf < 2; ++mf)
            #pragma unroll
            for (int hh = 0; hh < 2; ++hh) {
                float v = fmaxf(fmaxf(s[mf][0][hh * 2], s[mf][0][hh * 2 + 1]),
                                fmaxf(s[mf][1][hh * 2], s[mf][1][hh * 2 + 1]));
                v = fmaxf(v, __shfl_xor_sync(0xffffffffu, v, 1));
                v = fmaxf(v, __shfl_xor_sync(0xffffffffu, v, 2));
                pmax[mf][hh] = v;
            }
        if (tig == 0) {
            #pragma unroll
            for (int mf = 0; mf < 2; ++mf)
                #pragma unroll
                for (int hh = 0; hh < 2; ++hh)
                    Rm[wm * 128 + (mf * 16 + hh * 8 + gid) * 4 + wn] = pmax[mf][hh];
        }
        __syncthreads();

        float corr[2][2], psum[2][2];
        #pragma unroll
        for (int mf = 0; mf < 2; ++mf)
            #pragma unroll
            for (int hh = 0; hh < 2; ++hh) {
                float4 rv = *(const float4*)&Rm[wm * 128 + (mf * 16 + hh * 8 + gid) * 4];
                const float rmax = fmaxf(fmaxf(rv.x, rv.y), fmaxf(rv.z, rv.w));
                const float nm = fmaxf(m_[mf][hh], rmax);
                corr[mf][hh] = __expf(m_[mf][hh] - nm);
                m_[mf][hh] = nm;
                psum[mf][hh] = 0.0f;
            }

        // ---- exp + partial sums + P store (fp16) ----
        #pragma unroll
        for (int mf = 0; mf < 2; ++mf)
            #pragma unroll
            for (int nf = 0; nf < 2; ++nf)
                #pragma unroll
                for (int c = 0; c < 4; ++c) {
                    const int hh = c >> 1;
                    const float p = __expf(s[mf][nf][c] - m_[mf][hh]);
                    s[mf][nf][c] = p;
                    psum[mf][hh] += p;
                }
        #pragma unroll
        for (int mf = 0; mf < 2; ++mf)
            #pragma unroll
            for (int hh = 0; hh < 2; ++hh) {
                float v = psum[mf][hh];
                v += __shfl_xor_sync(0xffffffffu, v, 1);
                v += __shfl_xor_sync(0xffffffffu, v, 2);
                psum[mf][hh] = v;
            }
        if (tig == 0) {
            #pragma unroll
            for (int mf = 0; mf < 2; ++mf)
                #pragma unroll
                for (int hh = 0; hh < 2; ++hh)
                    Rs[wm * 128 + (mf * 16 + hh * 8 + gid) * 4 + wn] = psum[mf][hh];
        }
        #pragma unroll
        for (int mf = 0; mf < 2; ++mf)
            #pragma unroll
            for (int nf = 0; nf < 2; ++nf)
                #pragma unroll
                for (int hh = 0; hh < 2; ++hh) {
                    const int row = wm * 32 + mf * 16 + hh * 8 + gid;
                    const int col = wn * 16 + nf * 8 + 2 * tig;
                    *(half2*)&Ps[row * AST + col] =
                        __floats2half2_rn(s[mf][nf][hh * 2], s[mf][nf][hh * 2 + 1]);
                }
        __syncthreads();

        // ---- l update, O rescale, O += P @ V ----
        #pragma unroll
        for (int mf = 0; mf < 2; ++mf)
            #pragma unroll
            for (int hh = 0; hh < 2; ++hh) {
                float4 rv = *(const float4*)&Rs[wm * 128 + (mf * 16 + hh * 8 + gid) * 4];
                l_[mf][hh] = l_[mf][hh] * corr[mf][hh]
                           + (rv.x + rv.y + rv.z + rv.w);
            }
        #pragma unroll
        for (int mf = 0; mf < 2; ++mf)
            #pragma unroll
            for (int nf = 0; nf < 2; ++nf)
                #pragma unroll
                for (int c = 0; c < 4; ++c)
                    o[mf][nf][c] *= corr[mf][c >> 1];

        #pragma unroll
        for (int ks = 0; ks < 4; ++ks) {
            uint32_t pa[2][4], vb[4];
            #pragma unroll
            for (int mf = 0; mf < 2; ++mf) {
                const int row = wm * 32 + mf * 16 + arow_lo;
                LDSM_X4(pa[mf][0], pa[mf][1], pa[mf][2], pa[mf][3],
                        smem_u + AB_P + row * 144 + (2 * ks + ahi) * 16);
            }
            {
                const int jrow = ks * 16 + vrow_lo;
                LDSM_X4_T(vb[0], vb[1], vb[2], vb[3],
                          Vb + jrow * 144 + (wn * 2 + vhi) * 16);
            }
            #pragma unroll
            for (int mf = 0; mf < 2; ++mf) {
                MMA_F16(o[mf][0], pa[mf][0], pa[mf][1], pa[mf][2], pa[mf][3],
                        vb[0], vb[1]);
                MMA_F16(o[mf][1], pa[mf][0], pa[mf][1], pa[mf][2], pa[mf][3],
                        vb[2], vb[3]);
            }
        }
    }

    // ---- normalize + write fp16 for the O-projection ----
    #pragma unroll
    for (int mf = 0; mf < 2; ++mf)
        #pragma unroll
        for (int hh = 0; hh < 2; ++hh) {
            const float inv = 1.0f / l_[mf][hh];
            const size_t row = (size_t)(b * S_LEN + i0 + wm * 32 + mf * 16
                                        + hh * 8 + gid);
            #pragma unroll
            for (int nf = 0; nf < 2; ++nf) {
                const int col = h * DHEAD + wn * 16 + nf * 8 + 2 * tig;
                *(half2*)&g_ao[row * D_MODEL + col] =
                    __floats2half2_rn(o[mf][nf][hh * 2] * inv,
                                      o[mf][nf][hh * 2 + 1] * inv);
            }
        }
}

// ---------------------------------------------------------------------------
// Launch
// ---------------------------------------------------------------------------
extern "C" void kernel_launch(void* const* d_in, const int* in_sizes, int n_in,
                              void* d_out, int out_size)
{
    const float* x     = (const float*)d_in[0];
    const float* Wq    = (const float*)d_in[1];
    const float* bq    = (const float*)d_in[2];
    const float* Wk    = (const float*)d_in[3];
    const float* bk    = (const float*)d_in[4];
    const float* Wv    = (const float*)d_in[5];
    const float* bv    = (const float*)d_in[6];
    const float* Wo    = (const float*)d_in[7];
    const float* bo    = (const float*)d_in[8];
    const float* alibi = (const float*)d_in[9];
    float* out = (float*)d_out;

    __half *hx, *hwq, *hwk, *hwv, *hwo;
    cudaGetSymbolAddress((void**)&hx,  g_x);
    cudaGetSymbolAddress((void**)&hwq, g_wq);
    cudaGetSymbolAddress((void**)&hwk, g_wk);
    cudaGetSymbolAddress((void**)&hwv, g_wv);
    cudaGetSymbolAddress((void**)&hwo, g_wo);

    cudaFuncSetAttribute(qkv_kernel,
                         cudaFuncAttributeMaxDynamicSharedMemorySize, GEMM_SMEM);
    cudaFuncSetAttribute(oproj_kernel,
                         cudaFuncAttributeMaxDynamicSharedMemorySize, GEMM_SMEM);
    cudaFuncSetAttribute(attn_kernel,
                         cudaFuncAttributeMaxDynamicSharedMemorySize, ATTN_SMEM);

    to_half_kernel<<<1024, 256>>>(x,  hx,  MROWS * D_MODEL / 4);
    to_half_kernel<<<1024, 256>>>(Wq, hwq, D_MODEL * D_MODEL / 4);
    to_half_kernel<<<512,  256>>>(Wk, hwk, KVD * D_MODEL / 4);
    to_half_kernel<<<512,  256>>>(Wv, hwv, KVD * D_MODEL / 4);
    to_half_kernel<<<1024, 256>>>(Wo, hwo, D_MODEL * D_MODEL / 4);

    qkv_kernel<<<dim3(32, 24), 256, GEMM_SMEM>>>(bq, bk, bv);
    attn_kernel<<<dim3(S_LEN / 64, NHEADS, BATCH), 256, ATTN_SMEM>>>(alibi);
    oproj_kernel<<<dim3(32, 16), 256, GEMM_SMEM>>>(bo, out);
}